// round 12
// baseline (speedup 1.0000x reference)
#include <cuda_runtime.h>
#include <cuda_fp16.h>
#include <math.h>
#include <stdint.h>

#define Bb 4
#define Ss 4096
#define Dd 1024
#define Mm (Bb*Ss)       // 16384
#define NCHUNK 64
#define CLEN (Ss/NCHUNK) // 64

#define BM 128
#define BN 128
#define BK 32
#define NITER (Dd/BK)        // 32
#define STAGE_BYTES 16384    // A 8K | W 8K
#define NSTAGE 3
#define SMEM_DYN (NSTAGE*STAGE_BYTES)

// ---------------- scratch (device globals) ----------------
__device__ float g_Ac[Bb*NCHUNK*Dd];
__device__ float g_Bc[Bb*NCHUNK*Dd];
__device__ float g_carry[Bb*NCHUNK*Dd];

__device__ __align__(16) __half  g_dt16[(size_t)Mm*Dd];
__device__ __align__(16) __half2 g_gi[(size_t)Mm*Dd];     // .x=gate, .y=inp
__device__ __align__(16) __half  g_x16[(size_t)Mm*Dd];
__device__ __align__(16) __half  g_h16[(size_t)Mm*Dd];
__device__ __align__(16) __half  g_w16[3][(size_t)Dd*Dd];

// ---------------- asm helpers (portable sm_80-era only) ----------------
__device__ __forceinline__ uint32_t smem_u32(const void* p) {
    uint32_t a;
    asm("{ .reg .u64 t; cvta.to.shared.u64 t, %1; cvt.u32.u64 %0, t; }" : "=r"(a) : "l"(p));
    return a;
}

#define CP_ASYNC16(s, g) \
    asm volatile("cp.async.cg.shared.global [%0], [%1], 16;" :: "r"(s), "l"(g))
#define CP_COMMIT() asm volatile("cp.async.commit_group;")
#define CP_WAIT1()  asm volatile("cp.async.wait_group 1;")
#define CP_WAIT0()  asm volatile("cp.async.wait_group 0;")

#define LDSM_X4(r0, r1, r2, r3, addr) \
    asm volatile("ldmatrix.sync.aligned.m8n8.x4.shared.b16 {%0,%1,%2,%3}, [%4];" \
        : "=r"(r0), "=r"(r1), "=r"(r2), "=r"(r3) : "r"(addr))

// fp16-accumulate MMA: D(f16x2 pair) = A*B + C(f16x2 pair)
#define MMA_F16A(d, a, b0, b1, c0, c1) \
    asm volatile("mma.sync.aligned.m16n8k16.row.col.f16.f16.f16.f16 " \
        "{%0,%1}, {%2,%3,%4,%5}, {%6,%7}, {%8,%9};" \
        : "=r"((d)[0]), "=r"((d)[1]) \
        : "r"((a)[0]), "r"((a)[1]), "r"((a)[2]), "r"((a)[3]), \
          "r"(b0), "r"(b1), "r"(c0), "r"(c1))

// unpack f16x2 reg -> two floats
#define H2_TO_F2(lo, hi, u) \
    asm("{.reg .f16 l, h; mov.b32 {l, h}, %2; cvt.f32.f16 %0, l; cvt.f32.f16 %1, h;}" \
        : "=f"(lo), "=f"(hi) : "r"(u))

__device__ __forceinline__ float softplusf(float v) {
    return (v > 20.0f) ? v : log1pf(expf(v));
}

// smem offset for (row, 16B-chunk c): 64B rows, XOR swizzle for conflict-free ldmatrix
__device__ __forceinline__ uint32_t swz(int row, int c) {
    return (uint32_t)(row * 64 + ((c ^ ((row >> 1) & 3)) << 4));
}

// ---------------- fp32 -> fp16 conversions ----------------
__global__ void conv_x(const float* __restrict__ src)
{
    size_t i = ((size_t)blockIdx.x * blockDim.x + threadIdx.x) * 8;
    float4 v0 = *(const float4*)(src + i);
    float4 v1 = *(const float4*)(src + i + 4);
    __half2* d2 = (__half2*)(g_x16 + i);
    d2[0] = __floats2half2_rn(v0.x, v0.y);
    d2[1] = __floats2half2_rn(v0.z, v0.w);
    d2[2] = __floats2half2_rn(v1.x, v1.y);
    d2[3] = __floats2half2_rn(v1.z, v1.w);
}

__global__ void conv_w3(const float* __restrict__ w0, const float* __restrict__ w1,
                        const float* __restrict__ w2)
{
    int seg = blockIdx.y;
    const float* src = (seg == 0) ? w0 : (seg == 1) ? w1 : w2;
    __half* dst = g_w16[seg];
    size_t i = ((size_t)blockIdx.x * blockDim.x + threadIdx.x) * 8;
    float4 v0 = *(const float4*)(src + i);
    float4 v1 = *(const float4*)(src + i + 4);
    __half2* d2 = (__half2*)(dst + i);
    d2[0] = __floats2half2_rn(v0.x, v0.y);
    d2[1] = __floats2half2_rn(v0.z, v0.w);
    d2[2] = __floats2half2_rn(v1.x, v1.y);
    d2[3] = __floats2half2_rn(v1.z, v1.w);
}

// ---------------- fp16-acc tensor-core GEMM (fp32 fold every K=64) ----------------
// out[m,n] = sum_k A[m,k] * W[n,k]
// MODE 0: g_dt16 = softplus(acc + dt_b[n])       aux1 = dt_b
// MODE 1: gate/inp epilogue -> g_gi              aux2 = A_log, aux3 = h0, xptr = x
// MODE 2: out = acc + Dp[n]*x                    aux1 = Dp, xptr = x
template<int MODE>
__global__ __launch_bounds__(256, 1)
void gemm_f16(float* __restrict__ out,
              const float* __restrict__ aux1, const float* __restrict__ aux2,
              const float* __restrict__ aux3, const float* __restrict__ xptr)
{
    extern __shared__ char smem[];
    const __half* __restrict__ A = (MODE == 2) ? g_h16 : g_x16;
    const __half* __restrict__ W = g_w16[MODE];

    const int tid = threadIdx.x;
    const int wid = tid >> 5, lane = tid & 31;
    const int warpm = wid >> 2, warpn = wid & 3;      // 2 x 4 warps, 64x32 per warp
    const int bm = blockIdx.y * BM, bn = blockIdx.x * BN;
    const uint32_t sbase = smem_u32(smem);

    float acc[4][4][4];
    uint32_t a16[4][4][2];
    #pragma unroll
    for (int a = 0; a < 4; a++)
        #pragma unroll
        for (int b = 0; b < 4; b++) {
            #pragma unroll
            for (int c = 0; c < 4; c++) acc[a][b][c] = 0.0f;
            a16[a][b][0] = 0u; a16[a][b][1] = 0u;
        }
    const uint32_t z2 = 0u;

    auto load_stage = [&](int s, int it) {
        uint32_t st = sbase + (uint32_t)s * STAGE_BYTES;
        int k0 = it * BK;
        #pragma unroll
        for (int p = 0; p < 2; p++) {
            int lin = tid + p * 256;       // 0..511 chunks per array
            int row = lin >> 2, c = lin & 3;
            uint32_t soff = swz(row, c);
            size_t ga = (size_t)(bm + row) * Dd + k0 + c * 8;
            size_t gw = (size_t)(bn + row) * Dd + k0 + c * 8;
            CP_ASYNC16(st + soff,        A + ga);
            CP_ASYNC16(st + 8192 + soff, W + gw);
        }
        CP_COMMIT();
    };

    load_stage(0, 0);
    load_stage(1, 1);

    for (int i = 0; i < NITER; i++) {
        if (i == NITER - 1) CP_WAIT0(); else CP_WAIT1();
        __syncthreads();
        if (i + 2 < NITER) load_stage((i + 2) % NSTAGE, i + 2);

        uint32_t st = sbase + (uint32_t)(i % NSTAGE) * STAGE_BYTES;
        const bool chunk_start = ((i & 1) == 0);
        #pragma unroll
        for (int kk = 0; kk < 2; kk++) {       // two k16 steps per BK=32 stage
            uint32_t ah[4][4], bh[2][4];
            #pragma unroll
            for (int mi = 0; mi < 4; mi++) {
                int row = warpm * 64 + mi * 16 + (lane & 15);
                int c = kk * 2 + (lane >> 4);
                LDSM_X4(ah[mi][0], ah[mi][1], ah[mi][2], ah[mi][3], st + swz(row, c));
            }
            #pragma unroll
            for (int pr = 0; pr < 2; pr++) {
                int row = warpn * 32 + pr * 16 + (lane & 7) + (((lane >> 4) & 1) << 3);
                int c = kk * 2 + ((lane >> 3) & 1);
                LDSM_X4(bh[pr][0], bh[pr][1], bh[pr][2], bh[pr][3], st + 8192 + swz(row, c));
            }
            if (chunk_start && kk == 0) {
                #pragma unroll
                for (int mi = 0; mi < 4; mi++)
                    #pragma unroll
                    for (int ni = 0; ni < 4; ni++)
                        MMA_F16A(a16[mi][ni], ah[mi],
                                 bh[ni >> 1][(ni & 1) * 2], bh[ni >> 1][(ni & 1) * 2 + 1],
                                 z2, z2);
            } else {
                #pragma unroll
                for (int mi = 0; mi < 4; mi++)
                    #pragma unroll
                    for (int ni = 0; ni < 4; ni++)
                        MMA_F16A(a16[mi][ni], ah[mi],
                                 bh[ni >> 1][(ni & 1) * 2], bh[ni >> 1][(ni & 1) * 2 + 1],
                                 a16[mi][ni][0], a16[mi][ni][1]);
            }
        }
        if ((i & 1) == 1) {    // end of K=64 chunk: fold f16 partials into fp32
            #pragma unroll
            for (int mi = 0; mi < 4; mi++)
                #pragma unroll
                for (int ni = 0; ni < 4; ni++) {
                    float l0, h0v, l1, h1v;
                    H2_TO_F2(l0, h0v, a16[mi][ni][0]);
                    H2_TO_F2(l1, h1v, a16[mi][ni][1]);
                    acc[mi][ni][0] += l0;
                    acc[mi][ni][1] += h0v;
                    acc[mi][ni][2] += l1;
                    acc[mi][ni][3] += h1v;
                }
        }
    }

    // ---------------- epilogue ----------------
    const int mb0 = bm + warpm * 64;
    const int nb0 = bn + warpn * 32;
    #pragma unroll
    for (int mi = 0; mi < 4; mi++) {
        #pragma unroll
        for (int r = 0; r < 2; r++) {
            int m = mb0 + mi * 16 + (lane >> 2) + r * 8;
            size_t off = (size_t)m * Dd;
            #pragma unroll
            for (int ni = 0; ni < 4; ni++) {
                int n = nb0 + ni * 8 + (lane & 3) * 2;
                float v0 = acc[mi][ni][r * 2], v1 = acc[mi][ni][r * 2 + 1];
                if (MODE == 0) {
                    float2 bv = *(const float2*)&aux1[n];
                    *(__half2*)&g_dt16[off + n] =
                        __floats2half2_rn(softplusf(v0 + bv.x), softplusf(v1 + bv.y));
                } else if (MODE == 1) {
                    float2 dt = __half22float2(*(const __half2*)&g_dt16[off + n]);
                    float2 al2 = *(const float2*)&aux2[n];
                    float2 xv = *(const float2*)&xptr[off + n];
                    float2 gv, iv;
                    gv.x = expf(dt.x * (-expf(al2.x)));
                    gv.y = expf(dt.y * (-expf(al2.y)));
                    iv.x = dt.x * v0 * xv.x;
                    iv.y = dt.y * v1 * xv.y;
                    if ((m & (Ss - 1)) == 0) {
                        int b = m / Ss;
                        float2 h0v = *(const float2*)&aux3[(size_t)b * Dd + n];
                        iv.x += gv.x * h0v.x;
                        iv.y += gv.y * h0v.y;
                    }
                    g_gi[off + n]     = __floats2half2_rn(gv.x, iv.x);
                    g_gi[off + n + 1] = __floats2half2_rn(gv.y, iv.y);
                } else {
                    float2 dp = *(const float2*)&aux1[n];
                    float2 xv = *(const float2*)&xptr[off + n];
                    float2 o;
                    o.x = v0 + dp.x * xv.x;
                    o.y = v1 + dp.y * xv.y;
                    *(float2*)&out[off + n] = o;
                }
            }
        }
    }
}

// ---------------- chunked associative scan ----------------
__global__ void scan_pass1()
{
    int idx = blockIdx.x * blockDim.x + threadIdx.x;
    int d = idx & (Dd - 1);
    int chunk = (idx / Dd) & (NCHUNK - 1);
    int b = idx / (Dd * NCHUNK);
    size_t base = ((size_t)b * Ss + (size_t)chunk * CLEN) * Dd + d;
    float a = 1.0f, h = 0.0f;
    #pragma unroll 8
    for (int t = 0; t < CLEN; t++) {
        float2 gi = __half22float2(g_gi[base + (size_t)t * Dd]);
        a *= gi.x;
        h = gi.x * h + gi.y;
    }
    g_Ac[idx] = a;
    g_Bc[idx] = h;
}

__global__ void scan_pass2()
{
    int idx = blockIdx.x * blockDim.x + threadIdx.x;   // b*D + d
    int d = idx & (Dd - 1);
    int b = idx / Dd;
    const int base = b * NCHUNK * Dd + d;

    float A0[8], B0[8], A1[8], B1[8];
    #pragma unroll
    for (int j = 0; j < 8; j++) {
        A0[j] = g_Ac[base + j * Dd];
        B0[j] = g_Bc[base + j * Dd];
    }
    float c = 0.0f;
    #pragma unroll
    for (int ch = 0; ch < 8; ch++) {
        if (ch < 7) {
            #pragma unroll
            for (int j = 0; j < 8; j++) {
                A1[j] = g_Ac[base + ((ch + 1) * 8 + j) * Dd];
                B1[j] = g_Bc[base + ((ch + 1) * 8 + j) * Dd];
            }
        }
        #pragma unroll
        for (int j = 0; j < 8; j++) {
            g_carry[base + (ch * 8 + j) * Dd] = c;
            c = A0[j] * c + B0[j];
        }
        #pragma unroll
        for (int j = 0; j < 8; j++) { A0[j] = A1[j]; B0[j] = B1[j]; }
    }
}

__global__ void scan_pass3()
{
    int idx = blockIdx.x * blockDim.x + threadIdx.x;
    int d = idx & (Dd - 1);
    int chunk = (idx / Dd) & (NCHUNK - 1);
    int b = idx / (Dd * NCHUNK);
    size_t base = ((size_t)b * Ss + (size_t)chunk * CLEN) * Dd + d;
    float h = g_carry[idx];
    #pragma unroll 8
    for (int t = 0; t < CLEN; t++) {
        size_t o = base + (size_t)t * Dd;
        float2 gi = __half22float2(g_gi[o]);
        h = gi.x * h + gi.y;
        g_h16[o] = __float2half(h);
    }
}

extern "C" void kernel_launch(void* const* d_in, const int* in_sizes, int n_in,
                              void* d_out, int out_size)
{
    const float* x     = (const float*)d_in[0];
    const float* h0    = (const float*)d_in[1];
    const float* dt_w  = (const float*)d_in[2];
    const float* dt_b  = (const float*)d_in[3];
    const float* A_log = (const float*)d_in[4];
    const float* B_w   = (const float*)d_in[5];
    const float* C_w   = (const float*)d_in[6];
    const float* Dp    = (const float*)d_in[7];
    float* out = (float*)d_out;

    cudaFuncSetAttribute(gemm_f16<0>, cudaFuncAttributeMaxDynamicSharedMemorySize, SMEM_DYN);
    cudaFuncSetAttribute(gemm_f16<1>, cudaFuncAttributeMaxDynamicSharedMemorySize, SMEM_DYN);
    cudaFuncSetAttribute(gemm_f16<2>, cudaFuncAttributeMaxDynamicSharedMemorySize, SMEM_DYN);

    conv_x<<<((size_t)Mm * Dd) / 2048, 256>>>(x);
    conv_w3<<<dim3(((size_t)Dd * Dd) / 2048, 3), 256>>>(dt_w, B_w, C_w);

    dim3 grid(Dd / BN, Mm / BM);   // (8, 128)
    dim3 blk(256);

    gemm_f16<0><<<grid, blk, SMEM_DYN>>>(nullptr, dt_b, nullptr, nullptr, nullptr);
    gemm_f16<1><<<grid, blk, SMEM_DYN>>>(nullptr, nullptr, A_log, h0, x);
    scan_pass1<<<(Bb * NCHUNK * Dd) / 256, 256>>>();
    scan_pass2<<<(Bb * Dd) / 256, 256>>>();
    scan_pass3<<<(Bb * NCHUNK * Dd) / 256, 256>>>();
    gemm_f16<2><<<grid, blk, SMEM_DYN>>>(out, Dp, nullptr, nullptr, x);
}

// round 13
// speedup vs baseline: 1.2304x; 1.2304x over previous
#include <cuda_runtime.h>
#include <cuda_fp16.h>
#include <math.h>
#include <stdint.h>

#define Bb 4
#define Ss 4096
#define Dd 1024
#define Mm (Bb*Ss)       // 16384
#define NCHUNK 64
#define CLEN (Ss/NCHUNK) // 64

#define BM 128
#define BN 128
#define BK 32
#define NITER (Dd/BK)        // 32
#define STAGE_BYTES 16384    // A 8K | W 8K
#define NSTAGE 3
#define SMEM_DYN (NSTAGE*STAGE_BYTES)

#define NTILES 1024          // (Mm/BM)*(Dd/BN)
#define PGRID 296            // 148 SMs x occ 2, persistent

// ---------------- scratch (device globals) ----------------
__device__ float g_Ac[Bb*NCHUNK*Dd];
__device__ float g_Bc[Bb*NCHUNK*Dd];
__device__ float g_carry[Bb*NCHUNK*Dd];
__device__ unsigned g_tix[3];

__device__ __align__(16) __half  g_dt16[(size_t)Mm*Dd];
__device__ __align__(16) __half2 g_gi[(size_t)Mm*Dd];     // .x=gate, .y=inp
__device__ __align__(16) __half  g_x16[(size_t)Mm*Dd];
__device__ __align__(16) __half  g_h16[(size_t)Mm*Dd];
__device__ __align__(16) __half  g_w16[3][(size_t)Dd*Dd];

// ---------------- asm helpers (portable sm_80-era only) ----------------
__device__ __forceinline__ uint32_t smem_u32(const void* p) {
    uint32_t a;
    asm("{ .reg .u64 t; cvta.to.shared.u64 t, %1; cvt.u32.u64 %0, t; }" : "=r"(a) : "l"(p));
    return a;
}

#define CP_ASYNC16(s, g) \
    asm volatile("cp.async.cg.shared.global [%0], [%1], 16;" :: "r"(s), "l"(g))
#define CP_COMMIT() asm volatile("cp.async.commit_group;")
#define CP_WAIT1()  asm volatile("cp.async.wait_group 1;")
#define CP_WAIT0()  asm volatile("cp.async.wait_group 0;")

#define LDSM_X4(r0, r1, r2, r3, addr) \
    asm volatile("ldmatrix.sync.aligned.m8n8.x4.shared.b16 {%0,%1,%2,%3}, [%4];" \
        : "=r"(r0), "=r"(r1), "=r"(r2), "=r"(r3) : "r"(addr))

#define MMA_F16(c, a, b0, b1) \
    asm volatile("mma.sync.aligned.m16n8k16.row.col.f32.f16.f16.f32 " \
        "{%0,%1,%2,%3}, {%4,%5,%6,%7}, {%8,%9}, {%0,%1,%2,%3};" \
        : "+f"((c)[0]), "+f"((c)[1]), "+f"((c)[2]), "+f"((c)[3]) \
        : "r"((a)[0]), "r"((a)[1]), "r"((a)[2]), "r"((a)[3]), "r"(b0), "r"(b1))

__device__ __forceinline__ float softplusf(float v) {
    return (v > 20.0f) ? v : log1pf(expf(v));
}

// smem offset for (row, 16B-chunk c): 64B rows, XOR swizzle for conflict-free ldmatrix
__device__ __forceinline__ uint32_t swz(int row, int c) {
    return (uint32_t)(row * 64 + ((c ^ ((row >> 1) & 3)) << 4));
}

// ---------------- tile-counter reset (graph-replay safe) ----------------
__global__ void reset_tix()
{
    if (threadIdx.x < 3) g_tix[threadIdx.x] = PGRID;
}

// ---------------- fp32 -> fp16 conversions ----------------
__global__ void conv_x(const float* __restrict__ src)
{
    size_t i = ((size_t)blockIdx.x * blockDim.x + threadIdx.x) * 8;
    float4 v0 = *(const float4*)(src + i);
    float4 v1 = *(const float4*)(src + i + 4);
    __half2* d2 = (__half2*)(g_x16 + i);
    d2[0] = __floats2half2_rn(v0.x, v0.y);
    d2[1] = __floats2half2_rn(v0.z, v0.w);
    d2[2] = __floats2half2_rn(v1.x, v1.y);
    d2[3] = __floats2half2_rn(v1.z, v1.w);
}

__global__ void conv_w3(const float* __restrict__ w0, const float* __restrict__ w1,
                        const float* __restrict__ w2)
{
    int seg = blockIdx.y;
    const float* src = (seg == 0) ? w0 : (seg == 1) ? w1 : w2;
    __half* dst = g_w16[seg];
    size_t i = ((size_t)blockIdx.x * blockDim.x + threadIdx.x) * 8;
    float4 v0 = *(const float4*)(src + i);
    float4 v1 = *(const float4*)(src + i + 4);
    __half2* d2 = (__half2*)(dst + i);
    d2[0] = __floats2half2_rn(v0.x, v0.y);
    d2[1] = __floats2half2_rn(v0.z, v0.w);
    d2[2] = __floats2half2_rn(v1.x, v1.y);
    d2[3] = __floats2half2_rn(v1.z, v1.w);
}

// ---------------- fp16 tensor-core GEMM, persistent work-stealing ----------------
// out[m,n] = sum_k A[m,k] * W[n,k]
// MODE 0: g_dt16 = softplus(acc + dt_b[n])       aux1 = dt_b
// MODE 1: gate/inp epilogue -> g_gi              aux2 = A_log, aux3 = h0, xptr = x
// MODE 2: out = acc + Dp[n]*x                    aux1 = Dp, xptr = x
template<int MODE>
__global__ __launch_bounds__(256, 2)
void gemm_f16(float* __restrict__ out,
              const float* __restrict__ aux1, const float* __restrict__ aux2,
              const float* __restrict__ aux3, const float* __restrict__ xptr)
{
    extern __shared__ char smem[];
    __shared__ unsigned s_tile;
    const __half* __restrict__ A = (MODE == 2) ? g_h16 : g_x16;
    const __half* __restrict__ W = g_w16[MODE];

    const int tid = threadIdx.x;
    const int wid = tid >> 5, lane = tid & 31;
    const int warpm = wid >> 2, warpn = wid & 3;      // 2 x 4 warps, 64x32 per warp
    const uint32_t sbase = smem_u32(smem);

    unsigned tile = blockIdx.x;

    while (tile < NTILES) {
        const int bm = (int)(tile >> 3) * BM;
        const int bn = (int)(tile & 7) * BN;

        __syncthreads();    // previous tile's smem reads fully drained

        float acc[4][4][4];
        #pragma unroll
        for (int a = 0; a < 4; a++)
            #pragma unroll
            for (int b = 0; b < 4; b++)
                #pragma unroll
                for (int c = 0; c < 4; c++) acc[a][b][c] = 0.0f;

        auto load_stage = [&](int s, int it) {
            uint32_t st = sbase + (uint32_t)s * STAGE_BYTES;
            int k0 = it * BK;
            #pragma unroll
            for (int p = 0; p < 2; p++) {
                int lin = tid + p * 256;       // 0..511 chunks per array
                int row = lin >> 2, c = lin & 3;
                uint32_t soff = swz(row, c);
                size_t ga = (size_t)(bm + row) * Dd + k0 + c * 8;
                size_t gw = (size_t)(bn + row) * Dd + k0 + c * 8;
                CP_ASYNC16(st + soff,        A + ga);
                CP_ASYNC16(st + 8192 + soff, W + gw);
            }
            CP_COMMIT();
        };

        load_stage(0, 0);
        load_stage(1, 1);

        // steal next tile early (overlaps with mainloop)
        if (tid == 0) s_tile = atomicAdd(&g_tix[MODE], 1u);

        for (int i = 0; i < NITER; i++) {
            if (i == NITER - 1) CP_WAIT0(); else CP_WAIT1();
            __syncthreads();
            if (i + 2 < NITER) load_stage((i + 2) % NSTAGE, i + 2);

            uint32_t st = sbase + (uint32_t)(i % NSTAGE) * STAGE_BYTES;
            #pragma unroll
            for (int kk = 0; kk < 2; kk++) {       // two k16 steps per BK=32 stage
                uint32_t ah[4][4], bh[2][4];
                #pragma unroll
                for (int mi = 0; mi < 4; mi++) {
                    int row = warpm * 64 + mi * 16 + (lane & 15);
                    int c = kk * 2 + (lane >> 4);
                    LDSM_X4(ah[mi][0], ah[mi][1], ah[mi][2], ah[mi][3], st + swz(row, c));
                }
                #pragma unroll
                for (int pr = 0; pr < 2; pr++) {
                    int row = warpn * 32 + pr * 16 + (lane & 7) + (((lane >> 4) & 1) << 3);
                    int c = kk * 2 + ((lane >> 3) & 1);
                    LDSM_X4(bh[pr][0], bh[pr][1], bh[pr][2], bh[pr][3], st + 8192 + swz(row, c));
                }
                #pragma unroll
                for (int mi = 0; mi < 4; mi++)
                    #pragma unroll
                    for (int ni = 0; ni < 4; ni++)
                        MMA_F16(acc[mi][ni], ah[mi], bh[ni >> 1][(ni & 1) * 2], bh[ni >> 1][(ni & 1) * 2 + 1]);
            }
        }

        // ---------------- epilogue ----------------
        const int mb0 = bm + warpm * 64;
        const int nb0 = bn + warpn * 32;
        #pragma unroll
        for (int mi = 0; mi < 4; mi++) {
            #pragma unroll
            for (int r = 0; r < 2; r++) {
                int m = mb0 + mi * 16 + (lane >> 2) + r * 8;
                size_t off = (size_t)m * Dd;
                #pragma unroll
                for (int ni = 0; ni < 4; ni++) {
                    int n = nb0 + ni * 8 + (lane & 3) * 2;
                    float v0 = acc[mi][ni][r * 2], v1 = acc[mi][ni][r * 2 + 1];
                    if (MODE == 0) {
                        float2 bv = *(const float2*)&aux1[n];
                        *(__half2*)&g_dt16[off + n] =
                            __floats2half2_rn(softplusf(v0 + bv.x), softplusf(v1 + bv.y));
                    } else if (MODE == 1) {
                        float2 dt = __half22float2(*(const __half2*)&g_dt16[off + n]);
                        float2 al2 = *(const float2*)&aux2[n];
                        float2 xv = *(const float2*)&xptr[off + n];
                        float2 gv, iv;
                        gv.x = expf(dt.x * (-expf(al2.x)));
                        gv.y = expf(dt.y * (-expf(al2.y)));
                        iv.x = dt.x * v0 * xv.x;
                        iv.y = dt.y * v1 * xv.y;
                        if ((m & (Ss - 1)) == 0) {
                            int b = m / Ss;
                            float2 h0v = *(const float2*)&aux3[(size_t)b * Dd + n];
                            iv.x += gv.x * h0v.x;
                            iv.y += gv.y * h0v.y;
                        }
                        g_gi[off + n]     = __floats2half2_rn(gv.x, iv.x);
                        g_gi[off + n + 1] = __floats2half2_rn(gv.y, iv.y);
                    } else {
                        float2 dp = *(const float2*)&aux1[n];
                        float2 xv = *(const float2*)&xptr[off + n];
                        float2 o;
                        o.x = v0 + dp.x * xv.x;
                        o.y = v1 + dp.y * xv.y;
                        *(float2*)&out[off + n] = o;
                    }
                }
            }
        }

        __syncthreads();
        tile = s_tile;
    }
}

// ---------------- chunked associative scan ----------------
__global__ void scan_pass1()
{
    int idx = blockIdx.x * blockDim.x + threadIdx.x;
    int d = idx & (Dd - 1);
    int chunk = (idx / Dd) & (NCHUNK - 1);
    int b = idx / (Dd * NCHUNK);
    size_t base = ((size_t)b * Ss + (size_t)chunk * CLEN) * Dd + d;
    float a = 1.0f, h = 0.0f;
    #pragma unroll 8
    for (int t = 0; t < CLEN; t++) {
        float2 gi = __half22float2(g_gi[base + (size_t)t * Dd]);
        a *= gi.x;
        h = gi.x * h + gi.y;
    }
    g_Ac[idx] = a;
    g_Bc[idx] = h;
}

__global__ void scan_pass2()
{
    int idx = blockIdx.x * blockDim.x + threadIdx.x;   // b*D + d
    int d = idx & (Dd - 1);
    int b = idx / Dd;
    const int base = b * NCHUNK * Dd + d;

    float A0[8], B0[8], A1[8], B1[8];
    #pragma unroll
    for (int j = 0; j < 8; j++) {
        A0[j] = g_Ac[base + j * Dd];
        B0[j] = g_Bc[base + j * Dd];
    }
    float c = 0.0f;
    #pragma unroll
    for (int ch = 0; ch < 8; ch++) {
        if (ch < 7) {
            #pragma unroll
            for (int j = 0; j < 8; j++) {
                A1[j] = g_Ac[base + ((ch + 1) * 8 + j) * Dd];
                B1[j] = g_Bc[base + ((ch + 1) * 8 + j) * Dd];
            }
        }
        #pragma unroll
        for (int j = 0; j < 8; j++) {
            g_carry[base + (ch * 8 + j) * Dd] = c;
            c = A0[j] * c + B0[j];
        }
        #pragma unroll
        for (int j = 0; j < 8; j++) { A0[j] = A1[j]; B0[j] = B1[j]; }
    }
}

__global__ void scan_pass3()
{
    int idx = blockIdx.x * blockDim.x + threadIdx.x;
    int d = idx & (Dd - 1);
    int chunk = (idx / Dd) & (NCHUNK - 1);
    int b = idx / (Dd * NCHUNK);
    size_t base = ((size_t)b * Ss + (size_t)chunk * CLEN) * Dd + d;
    float h = g_carry[idx];
    #pragma unroll 8
    for (int t = 0; t < CLEN; t++) {
        size_t o = base + (size_t)t * Dd;
        float2 gi = __half22float2(g_gi[o]);
        h = gi.x * h + gi.y;
        g_h16[o] = __float2half(h);
    }
}

extern "C" void kernel_launch(void* const* d_in, const int* in_sizes, int n_in,
                              void* d_out, int out_size)
{
    const float* x     = (const float*)d_in[0];
    const float* h0    = (const float*)d_in[1];
    const float* dt_w  = (const float*)d_in[2];
    const float* dt_b  = (const float*)d_in[3];
    const float* A_log = (const float*)d_in[4];
    const float* B_w   = (const float*)d_in[5];
    const float* C_w   = (const float*)d_in[6];
    const float* Dp    = (const float*)d_in[7];
    float* out = (float*)d_out;

    cudaFuncSetAttribute(gemm_f16<0>, cudaFuncAttributeMaxDynamicSharedMemorySize, SMEM_DYN);
    cudaFuncSetAttribute(gemm_f16<1>, cudaFuncAttributeMaxDynamicSharedMemorySize, SMEM_DYN);
    cudaFuncSetAttribute(gemm_f16<2>, cudaFuncAttributeMaxDynamicSharedMemorySize, SMEM_DYN);

    reset_tix<<<1, 32>>>();
    conv_x<<<((size_t)Mm * Dd) / 2048, 256>>>(x);
    conv_w3<<<dim3(((size_t)Dd * Dd) / 2048, 3), 256>>>(dt_w, B_w, C_w);

    gemm_f16<0><<<PGRID, 256, SMEM_DYN>>>(nullptr, dt_b, nullptr, nullptr, nullptr);
    gemm_f16<1><<<PGRID, 256, SMEM_DYN>>>(nullptr, nullptr, A_log, h0, x);
    scan_pass1<<<(Bb * NCHUNK * Dd) / 256, 256>>>();
    scan_pass2<<<(Bb * Dd) / 256, 256>>>();
    scan_pass3<<<(Bb * NCHUNK * Dd) / 256, 256>>>();
    gemm_f16<2><<<PGRID, 256, SMEM_DYN>>>(out, Dp, nullptr, nullptr, x);
}

// round 15
// speedup vs baseline: 1.5252x; 1.2396x over previous
#include <cuda_runtime.h>
#include <cuda_fp16.h>
#include <math.h>
#include <stdint.h>

#define Bb 4
#define Ss 4096
#define Dd 1024
#define Mm (Bb*Ss)       // 16384
#define NCHUNK 64
#define CLEN (Ss/NCHUNK) // 64

#define BM 128
#define BN 128
#define BK 32
#define NITER (Dd/BK)        // 32
#define STAGE_BYTES 16384    // A 8K | W 8K
#define NSTAGE 3
#define SMEM_DYN (NSTAGE*STAGE_BYTES)

// ---------------- scratch (device globals) ----------------
__device__ __align__(16) __half  g_dt16[(size_t)Mm*Dd];
__device__ __align__(16) __half2 g_gi[(size_t)Mm*Dd];     // .x=gate, .y=inp
__device__ __align__(16) __half  g_x16[(size_t)Mm*Dd];
__device__ __align__(16) __half  g_h16[(size_t)Mm*Dd];
__device__ __align__(16) __half  g_w16[3][(size_t)Dd*Dd];

// ---------------- asm helpers (portable sm_80-era only) ----------------
__device__ __forceinline__ uint32_t smem_u32(const void* p) {
    uint32_t a;
    asm("{ .reg .u64 t; cvta.to.shared.u64 t, %1; cvt.u32.u64 %0, t; }" : "=r"(a) : "l"(p));
    return a;
}

#define CP_ASYNC16(s, g) \
    asm volatile("cp.async.cg.shared.global [%0], [%1], 16;" :: "r"(s), "l"(g))
#define CP_COMMIT() asm volatile("cp.async.commit_group;")
#define CP_WAIT1()  asm volatile("cp.async.wait_group 1;")
#define CP_WAIT0()  asm volatile("cp.async.wait_group 0;")

#define LDSM_X4(r0, r1, r2, r3, addr) \
    asm volatile("ldmatrix.sync.aligned.m8n8.x4.shared.b16 {%0,%1,%2,%3}, [%4];" \
        : "=r"(r0), "=r"(r1), "=r"(r2), "=r"(r3) : "r"(addr))

#define MMA_F16(c, a, b0, b1) \
    asm volatile("mma.sync.aligned.m16n8k16.row.col.f32.f16.f16.f32 " \
        "{%0,%1,%2,%3}, {%4,%5,%6,%7}, {%8,%9}, {%0,%1,%2,%3};" \
        : "+f"((c)[0]), "+f"((c)[1]), "+f"((c)[2]), "+f"((c)[3]) \
        : "r"((a)[0]), "r"((a)[1]), "r"((a)[2]), "r"((a)[3]), "r"(b0), "r"(b1))

__device__ __forceinline__ float softplusf(float v) {
    return (v > 20.0f) ? v : log1pf(expf(v));
}

// smem offset for (row, 16B-chunk c): 64B rows, XOR swizzle for conflict-free ldmatrix
__device__ __forceinline__ uint32_t swz(int row, int c) {
    return (uint32_t)(row * 64 + ((c ^ ((row >> 1) & 3)) << 4));
}

// ---------------- fp32 -> fp16 conversion, all four tensors in one launch ----------------
__global__ void conv_all(const float* __restrict__ x,  const float* __restrict__ w0,
                         const float* __restrict__ w1, const float* __restrict__ w2)
{
    const size_t NX = (size_t)Mm * Dd;       // 16,777,216
    const size_t NW = (size_t)Dd * Dd;       // 1,048,576
    size_t i = ((size_t)blockIdx.x * blockDim.x + threadIdx.x) * 8;
    const float* src;
    __half* dst;
    size_t off;
    if (i < NX)               { src = x;  dst = g_x16;    off = i; }
    else if (i < NX + NW)     { src = w0; dst = g_w16[0]; off = i - NX; }
    else if (i < NX + 2*NW)   { src = w1; dst = g_w16[1]; off = i - NX - NW; }
    else                      { src = w2; dst = g_w16[2]; off = i - NX - 2*NW; }
    float4 v0 = *(const float4*)(src + off);
    float4 v1 = *(const float4*)(src + off + 4);
    __half2* d2 = (__half2*)(dst + off);
    d2[0] = __floats2half2_rn(v0.x, v0.y);
    d2[1] = __floats2half2_rn(v0.z, v0.w);
    d2[2] = __floats2half2_rn(v1.x, v1.y);
    d2[3] = __floats2half2_rn(v1.z, v1.w);
}

// ---------------- fp16 single-pass tensor-core GEMM (R9 config) ----------------
// MODE 0: g_dt16 = softplus(acc + dt_b[n])       aux1 = dt_b
// MODE 1: gate/inp epilogue -> g_gi              aux2 = A_log, aux3 = h0, xptr = x
// MODE 2: out = acc + Dp[n]*x                    aux1 = Dp, xptr = x
template<int MODE>
__global__ __launch_bounds__(256, 2)
void gemm_f16(float* __restrict__ out,
              const float* __restrict__ aux1, const float* __restrict__ aux2,
              const float* __restrict__ aux3, const float* __restrict__ xptr)
{
    extern __shared__ char smem[];
    const __half* __restrict__ A = (MODE == 2) ? g_h16 : g_x16;
    const __half* __restrict__ W = g_w16[MODE];

    const int tid = threadIdx.x;
    const int wid = tid >> 5, lane = tid & 31;
    const int warpm = wid >> 2, warpn = wid & 3;      // 2 x 4 warps, 64x32 per warp
    const int bm = blockIdx.y * BM, bn = blockIdx.x * BN;
    const uint32_t sbase = smem_u32(smem);

    float acc[4][4][4];
    #pragma unroll
    for (int a = 0; a < 4; a++)
        #pragma unroll
        for (int b = 0; b < 4; b++)
            #pragma unroll
            for (int c = 0; c < 4; c++) acc[a][b][c] = 0.0f;

    auto load_stage = [&](int s, int it) {
        uint32_t st = sbase + (uint32_t)s * STAGE_BYTES;
        int k0 = it * BK;
        #pragma unroll
        for (int p = 0; p < 2; p++) {
            int lin = tid + p * 256;       // 0..511 chunks per array
            int row = lin >> 2, c = lin & 3;
            uint32_t soff = swz(row, c);
            size_t ga = (size_t)(bm + row) * Dd + k0 + c * 8;
            size_t gw = (size_t)(bn + row) * Dd + k0 + c * 8;
            CP_ASYNC16(st + soff,        A + ga);
            CP_ASYNC16(st + 8192 + soff, W + gw);
        }
        CP_COMMIT();
    };

    load_stage(0, 0);
    load_stage(1, 1);

    for (int i = 0; i < NITER; i++) {
        if (i == NITER - 1) CP_WAIT0(); else CP_WAIT1();
        __syncthreads();
        if (i + 2 < NITER) load_stage((i + 2) % NSTAGE, i + 2);

        uint32_t st = sbase + (uint32_t)(i % NSTAGE) * STAGE_BYTES;
        #pragma unroll
        for (int kk = 0; kk < 2; kk++) {       // two k16 steps per BK=32 stage
            uint32_t ah[4][4], bh[2][4];
            #pragma unroll
            for (int mi = 0; mi < 4; mi++) {
                int row = warpm * 64 + mi * 16 + (lane & 15);
                int c = kk * 2 + (lane >> 4);
                LDSM_X4(ah[mi][0], ah[mi][1], ah[mi][2], ah[mi][3], st + swz(row, c));
            }
            #pragma unroll
            for (int pr = 0; pr < 2; pr++) {
                int row = warpn * 32 + pr * 16 + (lane & 7) + (((lane >> 4) & 1) << 3);
                int c = kk * 2 + ((lane >> 3) & 1);
                LDSM_X4(bh[pr][0], bh[pr][1], bh[pr][2], bh[pr][3], st + 8192 + swz(row, c));
            }
            #pragma unroll
            for (int mi = 0; mi < 4; mi++)
                #pragma unroll
                for (int ni = 0; ni < 4; ni++)
                    MMA_F16(acc[mi][ni], ah[mi], bh[ni >> 1][(ni & 1) * 2], bh[ni >> 1][(ni & 1) * 2 + 1]);
        }
    }

    // ---------------- epilogue ----------------
    const int mb0 = bm + warpm * 64;
    const int nb0 = bn + warpn * 32;
    #pragma unroll
    for (int mi = 0; mi < 4; mi++) {
        #pragma unroll
        for (int r = 0; r < 2; r++) {
            int m = mb0 + mi * 16 + (lane >> 2) + r * 8;
            size_t off = (size_t)m * Dd;
            #pragma unroll
            for (int ni = 0; ni < 4; ni++) {
                int n = nb0 + ni * 8 + (lane & 3) * 2;
                float v0 = acc[mi][ni][r * 2], v1 = acc[mi][ni][r * 2 + 1];
                if (MODE == 0) {
                    float2 bv = *(const float2*)&aux1[n];
                    *(__half2*)&g_dt16[off + n] =
                        __floats2half2_rn(softplusf(v0 + bv.x), softplusf(v1 + bv.y));
                } else if (MODE == 1) {
                    float2 dt = __half22float2(*(const __half2*)&g_dt16[off + n]);
                    float2 al2 = *(const float2*)&aux2[n];
                    float2 xv = *(const float2*)&xptr[off + n];
                    float2 gv, iv;
                    gv.x = expf(dt.x * (-expf(al2.x)));
                    gv.y = expf(dt.y * (-expf(al2.y)));
                    iv.x = dt.x * v0 * xv.x;
                    iv.y = dt.y * v1 * xv.y;
                    if ((m & (Ss - 1)) == 0) {
                        int b = m / Ss;
                        float2 h0v = *(const float2*)&aux3[(size_t)b * Dd + n];
                        iv.x += gv.x * h0v.x;
                        iv.y += gv.y * h0v.y;
                    }
                    g_gi[off + n]     = __floats2half2_rn(gv.x, iv.x);
                    g_gi[off + n + 1] = __floats2half2_rn(gv.y, iv.y);
                } else {
                    float2 dp = *(const float2*)&aux1[n];
                    float2 xv = *(const float2*)&xptr[off + n];
                    float2 o;
                    o.x = v0 + dp.x * xv.x;
                    o.y = v1 + dp.y * xv.y;
                    *(float2*)&out[off + n] = o;
                }
            }
        }
    }
}

// ---------------- fused scan: one read of g_gi, block-local chunk scan ----------------
// block = 512 threads = 8 d-lanes x 64 chunks; one block covers (batch b, 8 d's).
// Each thread keeps its chunk's 64 half2 in registers.
__global__ __launch_bounds__(512)
void scan_fused()
{
    __shared__ float sA[NCHUNK][8];
    __shared__ float sB[NCHUNK][8];

    const int t = threadIdx.x;
    const int dl = t & 7, chunk = t >> 3;          // 8 d x 64 chunks
    const int b = blockIdx.x >> 7;                 // 4 batches
    const int d0 = (blockIdx.x & 127) * 8;         // 128 d-groups
    const size_t base = ((size_t)b * Ss + (size_t)chunk * CLEN) * Dd + d0 + dl;

    // phase 1: load chunk into registers, compute chunk transform (A, B)
    __half2 gi[CLEN];
    #pragma unroll
    for (int i = 0; i < CLEN; i++) gi[i] = g_gi[base + (size_t)i * Dd];

    float Av = 1.0f, Bv = 0.0f;
    #pragma unroll
    for (int i = 0; i < CLEN; i++) {
        float2 f = __half22float2(gi[i]);
        Av *= f.x;
        Bv = f.x * Bv + f.y;
    }

    // phase 2: Hillis-Steele inclusive scan over 64 chunk transforms
    sA[chunk][dl] = Av; sB[chunk][dl] = Bv;
    __syncthreads();
    #pragma unroll
    for (int off = 1; off < NCHUNK; off <<= 1) {
        float pa = 1.0f, pb = 0.0f;
        if (chunk >= off) { pa = sA[chunk - off][dl]; pb = sB[chunk - off][dl]; }
        __syncthreads();
        if (chunk >= off) {
            Bv = Av * pb + Bv;     // combine(left=prev, right=cur)
            Av = pa * Av;
            sA[chunk][dl] = Av; sB[chunk][dl] = Bv;
        }
        __syncthreads();
    }

    // carry into this chunk = inclusive-scan B of previous chunk
    float h = (chunk > 0) ? sB[chunk - 1][dl] : 0.0f;

    // phase 3: apply and write h16 from registers
    #pragma unroll
    for (int i = 0; i < CLEN; i++) {
        float2 f = __half22float2(gi[i]);
        h = f.x * h + f.y;
        g_h16[base + (size_t)i * Dd] = __float2half(h);
    }
}

extern "C" void kernel_launch(void* const* d_in, const int* in_sizes, int n_in,
                              void* d_out, int out_size)
{
    const float* x     = (const float*)d_in[0];
    const float* h0    = (const float*)d_in[1];
    const float* dt_w  = (const float*)d_in[2];
    const float* dt_b  = (const float*)d_in[3];
    const float* A_log = (const float*)d_in[4];
    const float* B_w   = (const float*)d_in[5];
    const float* C_w   = (const float*)d_in[6];
    const float* Dp    = (const float*)d_in[7];
    float* out = (float*)d_out;

    cudaFuncSetAttribute(gemm_f16<0>, cudaFuncAttributeMaxDynamicSharedMemorySize, SMEM_DYN);
    cudaFuncSetAttribute(gemm_f16<1>, cudaFuncAttributeMaxDynamicSharedMemorySize, SMEM_DYN);
    cudaFuncSetAttribute(gemm_f16<2>, cudaFuncAttributeMaxDynamicSharedMemorySize, SMEM_DYN);

    // ((Mm + 3*Dd) * Dd) / 8 elements-of-8 / 256 threads
    conv_all<<<(((size_t)Mm * Dd + 3 * (size_t)Dd * Dd) / 8) / 256, 256>>>(x, dt_w, B_w, C_w);

    dim3 grid(Dd / BN, Mm / BM);   // (8, 128)
    dim3 blk(256);

    gemm_f16<0><<<grid, blk, SMEM_DYN>>>(nullptr, dt_b, nullptr, nullptr, nullptr);
    gemm_f16<1><<<grid, blk, SMEM_DYN>>>(nullptr, nullptr, A_log, h0, x);
    scan_fused<<<Bb * (Dd / 8), 512>>>();
    gemm_f16<2><<<grid, blk, SMEM_DYN>>>(out, Dp, nullptr, nullptr, x);
}